// round 15
// baseline (speedup 1.0000x reference)
#include <cuda_runtime.h>
#include <cuda_fp16.h>
#include <cstdint>

#define NNODES 50000
#define MPAD   50048            // 391 * 128
#define NRELS  16
#define DIMS   128
#define NLAYER 2
#define NEDGE  600000
#define NQUERY 8192
#define PDIM   5
#define NCOL   (DIMS * (NRELS + 1))   // 2176
#define TCOL   (DIMS * NRELS)         // 2048
#define NTILES 17
#define MTILES 391                    // 17 * 23
#define MGROUP 23                     // M tiles per GEMM block
#define TILE_HALVES (128 * 128)       // fp16 per B tile (32 KB)
#define SCANB  49

// -------------------- scratch ------------------------------------------------
__device__ float  g_hA[(size_t)MPAD * DIMS];
__device__ float  g_hB[(size_t)MPAD * DIMS];
__device__ __half g_Ah[(size_t)MPAD * DIMS];              // fp16 row-major staged A
__device__ __half g_T[(size_t)MPAD * TCOL];
__device__ __half g_Bpack[NLAYER][(size_t)NCOL * DIMS];   // fragment-major fp16
__device__ uint4  g_Afrag[(size_t)MTILES * 2048];         // fragment-major fp16 A (12.8 MB, L2-resident)
__device__ int    g_cnt[NNODES * NRELS];
__device__ int    g_deg[NNODES];
__device__ int    g_off[NNODES + 1];
__device__ int    g_cur[NNODES];
__device__ int    g_bt[SCANB + 1];
__device__ uint32_t g_epack[NEDGE];   // src | (rel<<16)

// -------------------- helpers ------------------------------------------------
__device__ __forceinline__ uint32_t smem_u32(const void* p) {
    uint32_t a;
    asm("{ .reg .u64 t; cvta.to.shared.u64 t, %1; cvt.u32.u64 %0, t; }" : "=r"(a) : "l"(p));
    return a;
}
__device__ __forceinline__ void cp_async16(uint32_t saddr, const void* g) {
    asm volatile("cp.async.ca.shared.global [%0], [%1], 16;" :: "r"(saddr), "l"(g));
}
#define CP_COMMIT() asm volatile("cp.async.commit_group;")
#define CP_WAIT0()  asm volatile("cp.async.wait_group 0;")
#define BAR_SYNC(id, cnt) asm volatile("bar.sync %0, %1;" :: "r"(id), "r"(cnt) : "memory")

__device__ __forceinline__ uint32_t pack_h2(float a, float b) {
    __half2 h = __floats2half2_rn(a, b);
    return *reinterpret_cast<uint32_t*>(&h);
}
__device__ __forceinline__ void mma_f16(float c[4], uint4 a, uint32_t b0, uint32_t b1) {
    asm volatile(
        "mma.sync.aligned.m16n8k16.row.col.f32.f16.f16.f32 "
        "{%0,%1,%2,%3}, {%4,%5,%6,%7}, {%8,%9}, {%0,%1,%2,%3};"
        : "+f"(c[0]), "+f"(c[1]), "+f"(c[2]), "+f"(c[3])
        : "r"(a.x), "r"(a.y), "r"(a.z), "r"(a.w), "r"(b0), "r"(b1));
}

// -------------------- fused prep: weight packing + zero init ------------------
__global__ void prep_kernel(const float* __restrict__ Wself,
                            const float* __restrict__ Wrel) {
    int idx = blockIdx.x * blockDim.x + threadIdx.x;
    const int per_layer = NCOL * DIMS;
    const int total_pack = NLAYER * per_layer;
    if (idx < total_pack) {
        int l  = idx / per_layer;
        int hf = idx - l * per_layer;
        int e    = hf & 1;
        int w    = (hf >> 1) & 3;
        int lane = (hf >> 3) & 31;
        int kp2  = (hf >> 8) & 3;
        int cj   = (hf >> 10) & 15;
        int t    = hf >> 14;
        int qid = lane >> 2, rid = lane & 3;
        int kp   = kp2 * 2 + (w >> 1);
        int pair = w & 1;
        int k = kp * 16 + pair * 8 + rid * 2 + e;
        int n = t * 128 + cj * 8 + qid;
        float v;
        if (n < DIMS) {
            v = Wself[(l * DIMS + k) * DIMS + n];
        } else {
            int r = (n - DIMS) >> 7;
            int ee = (n - DIMS) & 127;
            v = Wrel[(((size_t)(l * NRELS + r) * DIMS) + k) * DIMS + ee];
        }
        g_Bpack[l][hf] = __float2half_rn(v);
    }
    if (idx < NNODES * NRELS) g_cnt[idx] = 0;
    if (idx < NNODES) g_deg[idx] = 0;
}

__global__ void hist_kernel(const int* __restrict__ dst, const int* __restrict__ et) {
    int e = blockIdx.x * blockDim.x + threadIdx.x;
    if (e >= NEDGE) return;
    int d = dst[e];
    atomicAdd(&g_cnt[d * NRELS + et[e]], 1);
    atomicAdd(&g_deg[d], 1);
}

// hierarchical scan (2 kernels; scanC sums block totals itself)
__global__ void scanA_kernel() {
    __shared__ int s[1024];
    int t = threadIdx.x;
    int i = blockIdx.x * 1024 + t;
    int v = (i < NNODES) ? g_deg[i] : 0;
    s[t] = v;
    __syncthreads();
#pragma unroll
    for (int off = 1; off < 1024; off <<= 1) {
        int x = (t >= off) ? s[t - off] : 0;
        __syncthreads();
        s[t] += x;
        __syncthreads();
    }
    if (i < NNODES) g_off[i + 1] = s[t];
    if (t == 1023) g_bt[blockIdx.x] = s[t];
}

__global__ void scanC_kernel() {
    __shared__ int base;
    int t = threadIdx.x;
    if (t == 0) {
        int run = 0;
        for (int b = 0; b < (int)blockIdx.x; b++) run += g_bt[b];
        base = run;
    }
    __syncthreads();
    int i = blockIdx.x * 1024 + t;
    if (i == 0) g_off[0] = 0;
    if (i < NNODES) {
        int o = g_off[i + 1] + base;
        g_off[i + 1] = o;
        g_cur[i] = o - g_deg[i];
    }
}

__global__ void scatter_kernel(const int* __restrict__ src,
                               const int* __restrict__ dst,
                               const int* __restrict__ et) {
    int e = blockIdx.x * blockDim.x + threadIdx.x;
    if (e >= NEDGE) return;
    int d = dst[e];
    int pos = atomicAdd(&g_cur[d], 1);
    g_epack[pos] = (uint32_t)src[e] | ((uint32_t)et[e] << 16);
}

// -------------------- grouped aggregation (lane-parallel, no atomics) --------
__global__ void __launch_bounds__(256)
group_agg_kernel(float* __restrict__ hn, __half* __restrict__ ah) {
    int warp = (blockIdx.x * blockDim.x + threadIdx.x) >> 5;
    int lane = threadIdx.x & 31;
    if (warp >= NNODES) return;
    int beg = g_off[warp];
    int end = g_off[warp + 1];
    if (!ah && beg == end) return;

    float inv = 0.f;
    if (lane < NRELS) {
        int c = g_cnt[warp * NRELS + lane];
        inv = (c > 0) ? (1.0f / (float)c) : 0.f;
    }

    float4 acc = make_float4(0.f, 0.f, 0.f, 0.f);
    for (int base = beg; base < end; base += 32) {
        int m = min(32, end - base);
        uint32_t myp = (lane < m) ? g_epack[base + lane] : 0u;
        for (int i = 0; i < m; i++) {
            uint32_t p = __shfl_sync(0xFFFFFFFFu, myp, i);
            int s = p & 0xFFFF;
            int r = p >> 16;
            float w = __shfl_sync(0xFFFFFFFFu, inv, r);
            uint2 u = *reinterpret_cast<const uint2*>(
                g_T + (size_t)s * TCOL + r * DIMS + lane * 4);
            float2 f0 = __half22float2(*reinterpret_cast<__half2*>(&u.x));
            float2 f1 = __half22float2(*reinterpret_cast<__half2*>(&u.y));
            acc.x += w * f0.x; acc.y += w * f0.y;
            acc.z += w * f1.x; acc.w += w * f1.y;
        }
    }
    float* o = hn + (size_t)warp * DIMS + lane * 4;
    float4 cur = *reinterpret_cast<float4*>(o);
    cur.x += acc.x; cur.y += acc.y; cur.z += acc.z; cur.w += acc.w;
    if (ah) {
        cur.x = fmaxf(cur.x, 0.f); cur.y = fmaxf(cur.y, 0.f);
        cur.z = fmaxf(cur.z, 0.f); cur.w = fmaxf(cur.w, 0.f);
        uint2 h;
        h.x = pack_h2(cur.x, cur.y);
        h.y = pack_h2(cur.z, cur.w);
        *reinterpret_cast<uint2*>(ah + (size_t)warp * DIMS + lane * 4) = h;
    } else {
        *reinterpret_cast<float4*>(o) = cur;
    }
}

// -------------------- A conversion to fragment-major fp16 --------------------
__global__ void __launch_bounds__(512)
convA_kernel(const __half* __restrict__ Ah,
             const int* __restrict__ nid,
             const float* __restrict__ emb,
             int mode) {
    extern __shared__ __half scrh[];
    const int tid = threadIdx.x;
    const int m0 = blockIdx.x * 128;

    if (mode == 0) {
        for (int i = tid; i < 128 * 32; i += 512) {
            int r = i >> 5, c4 = i & 31;
            int m = m0 + r;
            int id = nid[m < NNODES ? m : NNODES - 1];
            float4 v = reinterpret_cast<const float4*>(emb + (size_t)id * DIMS)[c4];
            uint2 h;
            h.x = pack_h2(v.x, v.y);
            h.y = pack_h2(v.z, v.w);
            *reinterpret_cast<uint2*>(&scrh[r * 128 + c4 * 4]) = h;
        }
    } else {
        for (int i = tid; i < 128 * 16; i += 512) {
            int r = i >> 4, c8 = i & 15;
            uint4 v = reinterpret_cast<const uint4*>(Ah + (size_t)(m0 + r) * DIMS)[c8];
            *reinterpret_cast<uint4*>(&scrh[r * 128 + c8 * 8]) = v;
        }
    }
    __syncthreads();

    uint4* outp = g_Afrag + (size_t)blockIdx.x * 2048;
#pragma unroll
    for (int it = 0; it < 4; it++) {
        int item = tid + it * 512;
        int bi = item >> 8;
        int kk = (item >> 5) & 7;
        int ln = item & 31;
        int q = ln >> 2, rd = ln & 3;
        int r0 = bi * 16 + q;
        int c0 = kk * 16 + rd * 2;
        uint4 w;
        w.x = *reinterpret_cast<uint32_t*>(&scrh[r0 * 128 + c0]);
        w.y = *reinterpret_cast<uint32_t*>(&scrh[(r0 + 8) * 128 + c0]);
        w.z = *reinterpret_cast<uint32_t*>(&scrh[r0 * 128 + c0 + 8]);
        w.w = *reinterpret_cast<uint32_t*>(&scrh[(r0 + 8) * 128 + c0 + 8]);
        outp[item] = w;
    }
}

// -------------------- B-stationary GEMM, 2 CTAs/SM ----------------------------
// grid (17 N-tiles, 17 M-groups) = 289 blocks; 2 CTAs/SM -> 0.98 waves.
// 512 thr = 4 groups (32 M rows) x 4 warps (32 N cols). 2-stage A double buffer
// per group with named barriers; B read from smem per kp2 (no reg hoist, <=64 regs).
// smem: A[g][stage] = (g*2+stage)*8192 (64 KB) | B at 65536 (32 KB) = 96 KB
#define GEMM_SMEM 98304

__global__ void __launch_bounds__(512, 2)
gemm_kernel(const uint4* __restrict__ Afrag,
            const __half* __restrict__ B,
            __half* __restrict__ T,
            float* __restrict__ hn) {
    extern __shared__ char smc[];
    uint4* Bsm = reinterpret_cast<uint4*>(smc + 65536);
    const uint32_t sb = smem_u32(smc);

    const int tid  = threadIdx.x;
    const int nt   = blockIdx.x;
    const int mg   = blockIdx.y;
    const int mt0  = mg * MGROUP;
    const int wid  = tid >> 5;
    const int grp  = wid >> 2;          // 0..3  (M strip)
    const int wn   = wid & 3;           // 0..3  (N strip)
    const int ltid = tid & 127;
    const int lane = tid & 31;
    const int qid  = lane >> 2;
    const int rid  = lane & 3;

    const uint32_t a_base = sb + (uint32_t)grp * 2u * 8192u;   // 2 stages
    const uint4* Atile    = Afrag + (size_t)grp * 512;

    // B tile (all threads)
    {
        const __half* Bt = B + (size_t)nt * TILE_HALVES;
#pragma unroll
        for (int it = 0; it < 4; it++) {
            int i = tid + it * 512;
            cp_async16(sb + 65536u + (uint32_t)i * 16u, Bt + i * 8);
        }
        CP_COMMIT();
    }
    // A stage 0 (tile mt0), group threads
    {
        const uint4* At = Atile + (size_t)mt0 * 2048;
#pragma unroll
        for (int j = 0; j < 4; j++)
            cp_async16(a_base + (uint32_t)(ltid + j * 128) * 16u, At + ltid + j * 128);
        CP_COMMIT();
    }
    CP_WAIT0();
    __syncthreads();        // B + A0 visible block-wide

    const int gc0 = nt * 128 + wn * 32;

    for (int mi = 0; mi < MGROUP; mi++) {
        if (mi > 0) CP_WAIT0();          // load(mi) (issued last iter) complete
        BAR_SYNC(1 + grp, 128);          // group: compute(mi-1) done, load(mi) visible

        if (mi + 1 < MGROUP) {           // refill the stage compute(mi-1) just freed
            const uint4* At = Atile + (size_t)(mt0 + mi + 1) * 2048;
            uint32_t sbase = a_base + (uint32_t)((mi + 1) & 1) * 8192u;
#pragma unroll
            for (int j = 0; j < 4; j++)
                cp_async16(sbase + (uint32_t)(ltid + j * 128) * 16u,
                           At + ltid + j * 128);
            CP_COMMIT();
        }

        const uint4* Acur = reinterpret_cast<const uint4*>(
            smc + (size_t)grp * 2 * 8192 + (size_t)(mi & 1) * 8192);

        float c[2][4][4];
#pragma unroll
        for (int im = 0; im < 2; im++)
#pragma unroll
            for (int jn = 0; jn < 4; jn++)
#pragma unroll
                for (int q = 0; q < 4; q++) c[im][jn][q] = 0.f;

#pragma unroll
        for (int kp2 = 0; kp2 < 4; kp2++) {
            uint4 bf[4];
#pragma unroll
            for (int jn = 0; jn < 4; jn++)
                bf[jn] = Bsm[(((wn * 4 + jn) * 4 + kp2) << 5) + lane];
#pragma unroll
            for (int sub = 0; sub < 2; sub++) {
                int kk = kp2 * 2 + sub;
                uint4 af[2];
                af[0] = Acur[((0 * 8 + kk) << 5) + lane];
                af[1] = Acur[((1 * 8 + kk) << 5) + lane];
#pragma unroll
                for (int im = 0; im < 2; im++)
#pragma unroll
                    for (int jn = 0; jn < 4; jn++) {
                        uint32_t b0 = sub ? bf[jn].z : bf[jn].x;
                        uint32_t b1 = sub ? bf[jn].w : bf[jn].y;
                        mma_f16(c[im][jn], af[im], b0, b1);
                    }
            }
        }

        const int m0 = (mt0 + mi) * 128;
        if (nt == 0) {
#pragma unroll
            for (int im = 0; im < 2; im++) {
                int row = m0 + grp * 32 + im * 16 + qid;
#pragma unroll
                for (int jn = 0; jn < 4; jn++) {
                    int col = gc0 + jn * 8 + 2 * rid;
                    *reinterpret_cast<float2*>(hn + (size_t)row * DIMS + col)
                        = make_float2(c[im][jn][0], c[im][jn][1]);
                    *reinterpret_cast<float2*>(hn + (size_t)(row + 8) * DIMS + col)
                        = make_float2(c[im][jn][2], c[im][jn][3]);
                }
            }
        } else {
            int cb = gc0 - DIMS;
#pragma unroll
            for (int im = 0; im < 2; im++) {
                int row = m0 + grp * 32 + im * 16 + qid;
#pragma unroll
                for (int jn = 0; jn < 4; jn++) {
                    int col = cb + jn * 8 + 2 * rid;
                    *reinterpret_cast<__half2*>(T + (size_t)row * TCOL + col)
                        = __floats2half2_rn(c[im][jn][0], c[im][jn][1]);
                    *reinterpret_cast<__half2*>(T + (size_t)(row + 8) * TCOL + col)
                        = __floats2half2_rn(c[im][jn][2], c[im][jn][3]);
                }
            }
        }
    }
}

// -------------------- scoring (relu fused) -----------------------------------
__global__ void score_kernel(const float* __restrict__ h,
                             const int* __restrict__ heads,
                             const int* __restrict__ rels,
                             const int* __restrict__ tails,
                             const float* __restrict__ rel_emb,
                             const float* __restrict__ path_feat,
                             const int* __restrict__ task_idx,
                             const float* __restrict__ delta_w,
                             const float* __restrict__ lambda_logit,
                             const float* __restrict__ rule_init,
                             float* __restrict__ out) {
    int warp = (blockIdx.x * blockDim.x + threadIdx.x) >> 5;
    int lane = threadIdx.x & 31;
    if (warp >= NQUERY) return;
    int hh = heads[warp], rr = rels[warp], tt = tails[warp];
    float4 a = reinterpret_cast<const float4*>(h + (size_t)hh * DIMS)[lane];
    float4 r = reinterpret_cast<const float4*>(rel_emb + (size_t)rr * DIMS)[lane];
    float4 b = reinterpret_cast<const float4*>(h + (size_t)tt * DIMS)[lane];
    a.x = fmaxf(a.x, 0.f); a.y = fmaxf(a.y, 0.f); a.z = fmaxf(a.z, 0.f); a.w = fmaxf(a.w, 0.f);
    b.x = fmaxf(b.x, 0.f); b.y = fmaxf(b.y, 0.f); b.z = fmaxf(b.z, 0.f); b.w = fmaxf(b.w, 0.f);
    float s = a.x * r.x * b.x + a.y * r.y * b.y + a.z * r.z * b.z + a.w * r.w * b.w;
#pragma unroll
    for (int off = 16; off > 0; off >>= 1)
        s += __shfl_xor_sync(0xFFFFFFFFu, s, off);
    if (lane == 0) {
        int idx = task_idx[0];
        float sp = 0.f;
#pragma unroll
        for (int p = 0; p < PDIM; p++)
            sp += path_feat[warp * PDIM + p] * (rule_init[idx * PDIM + p] + delta_w[idx * PDIM + p]);
        float lam = 1.0f / (1.0f + __expf(-lambda_logit[idx]));
        out[warp] = lam * s + (1.0f - lam) * sp;
    }
}

// -------------------- launcher -----------------------------------------------
extern "C" void kernel_launch(void* const* d_in, const int* in_sizes, int n_in,
                              void* d_out, int out_size) {
    const int*   node_ids   = (const int*)d_in[0];
    const int*   edge_index = (const int*)d_in[1];
    const int*   edge_type  = (const int*)d_in[2];
    const int*   heads      = (const int*)d_in[3];
    const int*   rels       = (const int*)d_in[4];
    const int*   tails      = (const int*)d_in[5];
    const float* path_feat  = (const float*)d_in[6];
    const int*   task_idx   = (const int*)d_in[7];
    const float* entity_emb = (const float*)d_in[8];
    const float* rel_emb    = (const float*)d_in[9];
    const float* W_self     = (const float*)d_in[10];
    const float* W_rel      = (const float*)d_in[11];
    const float* delta_w    = (const float*)d_in[12];
    const float* lambda_lg  = (const float*)d_in[13];
    const float* rule_init  = (const float*)d_in[14];
    float*       out        = (float*)d_out;

    const int* src = edge_index;
    const int* dst = edge_index + NEDGE;

    float *hA, *hB;
    __half *T, *Bpack, *Ah;
    uint4* Afrag;
    cudaGetSymbolAddress((void**)&hA, g_hA);
    cudaGetSymbolAddress((void**)&hB, g_hB);
    cudaGetSymbolAddress((void**)&Ah, g_Ah);
    cudaGetSymbolAddress((void**)&T, g_T);
    cudaGetSymbolAddress((void**)&Bpack, g_Bpack);
    cudaGetSymbolAddress((void**)&Afrag, g_Afrag);

    const int TPB = 256;
    cudaFuncSetAttribute(gemm_kernel,
                         cudaFuncAttributeMaxDynamicSharedMemorySize, GEMM_SMEM);
    cudaFuncSetAttribute(convA_kernel,
                         cudaFuncAttributeMaxDynamicSharedMemorySize, 32768);

    prep_kernel<<<(NNODES * NRELS + TPB - 1) / TPB, TPB>>>(W_self, W_rel);
    hist_kernel<<<(NEDGE + TPB - 1) / TPB, TPB>>>(dst, edge_type);
    scanA_kernel<<<SCANB, 1024>>>();
    scanC_kernel<<<SCANB, 1024>>>();
    scatter_kernel<<<(NEDGE + TPB - 1) / TPB, TPB>>>(src, dst, edge_type);

    dim3 ggrid(NTILES, NTILES);    // 17 x 17 = 289 blocks, 2 CTAs/SM
    const int agg_blocks = (NNODES * 32 + TPB - 1) / TPB;

    // layer 1: A gathered from entity_emb; agg writes relu'd fp16 rows to Ah
    convA_kernel<<<MTILES, 512, 32768>>>(nullptr, node_ids, entity_emb, 0);
    gemm_kernel<<<ggrid, 512, GEMM_SMEM>>>(Afrag, Bpack, T, hB);
    group_agg_kernel<<<agg_blocks, TPB>>>(hB, Ah);
    // layer 2: A from fp16 Ah; agg writes fp32 hA (scoring applies relu)
    convA_kernel<<<MTILES, 512, 32768>>>(Ah, nullptr, nullptr, 1);
    gemm_kernel<<<ggrid, 512, GEMM_SMEM>>>(Afrag, Bpack + (size_t)NCOL * DIMS, T, hA);
    group_agg_kernel<<<agg_blocks, TPB>>>(hA, nullptr);

    score_kernel<<<(NQUERY * 32 + TPB - 1) / TPB, TPB>>>(
        hA, heads, rels, tails, rel_emb, path_feat, task_idx,
        delta_w, lambda_lg, rule_init, out);
}

// round 16
// speedup vs baseline: 1.6251x; 1.6251x over previous
#include <cuda_runtime.h>
#include <cuda_fp16.h>
#include <cstdint>

#define NNODES 50000
#define MPAD   50048            // 391 * 128
#define NRELS  16
#define DIMS   128
#define NLAYER 2
#define NEDGE  600000
#define NQUERY 8192
#define PDIM   5
#define NCOL   (DIMS * (NRELS + 1))   // 2176
#define TCOL   (DIMS * NRELS)         // 2048
#define NTILES 17
#define MTILES 391                    // 17 * 23
#define MGROUP 23                     // M tiles per GEMM block
#define TILE_HALVES (128 * 128)       // fp16 per B tile (32 KB)
#define SCANB  49

// -------------------- scratch ------------------------------------------------
__device__ float  g_hA[(size_t)MPAD * DIMS];
__device__ float  g_hB[(size_t)MPAD * DIMS];
__device__ __half g_Ah[(size_t)MPAD * DIMS];              // fp16 row-major staged A
__device__ __half g_T[(size_t)MPAD * TCOL];
__device__ __half g_Bpack[NLAYER][(size_t)NCOL * DIMS];   // fragment-major fp16
__device__ uint4  g_Afrag[(size_t)MTILES * 2048];         // fragment-major fp16 A
__device__ int    g_cnt[NNODES * NRELS];
__device__ int    g_deg[NNODES];
__device__ int    g_off[NNODES + 1];
__device__ int    g_cur[NNODES];
__device__ int    g_bt[SCANB + 1];
__device__ uint32_t g_epack[NEDGE];   // src | (rel<<16)

// -------------------- helpers ------------------------------------------------
__device__ __forceinline__ uint32_t smem_u32(const void* p) {
    uint32_t a;
    asm("{ .reg .u64 t; cvta.to.shared.u64 t, %1; cvt.u32.u64 %0, t; }" : "=r"(a) : "l"(p));
    return a;
}
__device__ __forceinline__ void cp_async16(uint32_t saddr, const void* g) {
    asm volatile("cp.async.ca.shared.global [%0], [%1], 16;" :: "r"(saddr), "l"(g));
}
#define CP_COMMIT() asm volatile("cp.async.commit_group;")
#define CP_WAIT0()  asm volatile("cp.async.wait_group 0;")
#define CP_WAIT1()  asm volatile("cp.async.wait_group 1;")
#define CP_WAIT2()  asm volatile("cp.async.wait_group 2;")
#define BAR_SYNC(id, cnt) asm volatile("bar.sync %0, %1;" :: "r"(id), "r"(cnt) : "memory")

__device__ __forceinline__ uint32_t pack_h2(float a, float b) {
    __half2 h = __floats2half2_rn(a, b);
    return *reinterpret_cast<uint32_t*>(&h);
}
__device__ __forceinline__ void mma_f16(float c[4], uint4 a, uint32_t b0, uint32_t b1) {
    asm volatile(
        "mma.sync.aligned.m16n8k16.row.col.f32.f16.f16.f32 "
        "{%0,%1,%2,%3}, {%4,%5,%6,%7}, {%8,%9}, {%0,%1,%2,%3};"
        : "+f"(c[0]), "+f"(c[1]), "+f"(c[2]), "+f"(c[3])
        : "r"(a.x), "r"(a.y), "r"(a.z), "r"(a.w), "r"(b0), "r"(b1));
}

// -------------------- fused prep: weight packing + zero init ------------------
__global__ void prep_kernel(const float* __restrict__ Wself,
                            const float* __restrict__ Wrel) {
    int idx = blockIdx.x * blockDim.x + threadIdx.x;
    const int per_layer = NCOL * DIMS;
    const int total_pack = NLAYER * per_layer;
    if (idx < total_pack) {
        int l  = idx / per_layer;
        int hf = idx - l * per_layer;
        int e    = hf & 1;
        int w    = (hf >> 1) & 3;
        int lane = (hf >> 3) & 31;
        int kp2  = (hf >> 8) & 3;
        int cj   = (hf >> 10) & 15;
        int t    = hf >> 14;
        int qid = lane >> 2, rid = lane & 3;
        int kp   = kp2 * 2 + (w >> 1);
        int pair = w & 1;
        int k = kp * 16 + pair * 8 + rid * 2 + e;
        int n = t * 128 + cj * 8 + qid;
        float v;
        if (n < DIMS) {
            v = Wself[(l * DIMS + k) * DIMS + n];
        } else {
            int r = (n - DIMS) >> 7;
            int ee = (n - DIMS) & 127;
            v = Wrel[(((size_t)(l * NRELS + r) * DIMS) + k) * DIMS + ee];
        }
        g_Bpack[l][hf] = __float2half_rn(v);
    }
    if (idx < NNODES * NRELS) g_cnt[idx] = 0;
    if (idx < NNODES) g_deg[idx] = 0;
}

__global__ void hist_kernel(const int* __restrict__ dst, const int* __restrict__ et) {
    int e = blockIdx.x * blockDim.x + threadIdx.x;
    if (e >= NEDGE) return;
    int d = dst[e];
    atomicAdd(&g_cnt[d * NRELS + et[e]], 1);
    atomicAdd(&g_deg[d], 1);
}

// hierarchical scan (2 kernels; scanC sums block totals itself)
__global__ void scanA_kernel() {
    __shared__ int s[1024];
    int t = threadIdx.x;
    int i = blockIdx.x * 1024 + t;
    int v = (i < NNODES) ? g_deg[i] : 0;
    s[t] = v;
    __syncthreads();
#pragma unroll
    for (int off = 1; off < 1024; off <<= 1) {
        int x = (t >= off) ? s[t - off] : 0;
        __syncthreads();
        s[t] += x;
        __syncthreads();
    }
    if (i < NNODES) g_off[i + 1] = s[t];
    if (t == 1023) g_bt[blockIdx.x] = s[t];
}

__global__ void scanC_kernel() {
    __shared__ int base;
    int t = threadIdx.x;
    if (t == 0) {
        int run = 0;
        for (int b = 0; b < (int)blockIdx.x; b++) run += g_bt[b];
        base = run;
    }
    __syncthreads();
    int i = blockIdx.x * 1024 + t;
    if (i == 0) g_off[0] = 0;
    if (i < NNODES) {
        int o = g_off[i + 1] + base;
        g_off[i + 1] = o;
        g_cur[i] = o - g_deg[i];
    }
}

__global__ void scatter_kernel(const int* __restrict__ src,
                               const int* __restrict__ dst,
                               const int* __restrict__ et) {
    int e = blockIdx.x * blockDim.x + threadIdx.x;
    if (e >= NEDGE) return;
    int d = dst[e];
    int pos = atomicAdd(&g_cur[d], 1);
    g_epack[pos] = (uint32_t)src[e] | ((uint32_t)et[e] << 16);
}

// -------------------- grouped aggregation (lane-parallel, no atomics) --------
__global__ void __launch_bounds__(256)
group_agg_kernel(float* __restrict__ hn, __half* __restrict__ ah) {
    int warp = (blockIdx.x * blockDim.x + threadIdx.x) >> 5;
    int lane = threadIdx.x & 31;
    if (warp >= NNODES) return;
    int beg = g_off[warp];
    int end = g_off[warp + 1];
    if (!ah && beg == end) return;

    float inv = 0.f;
    if (lane < NRELS) {
        int c = g_cnt[warp * NRELS + lane];
        inv = (c > 0) ? (1.0f / (float)c) : 0.f;
    }

    float4 acc = make_float4(0.f, 0.f, 0.f, 0.f);
    for (int base = beg; base < end; base += 32) {
        int m = min(32, end - base);
        uint32_t myp = (lane < m) ? g_epack[base + lane] : 0u;
        for (int i = 0; i < m; i++) {
            uint32_t p = __shfl_sync(0xFFFFFFFFu, myp, i);
            int s = p & 0xFFFF;
            int r = p >> 16;
            float w = __shfl_sync(0xFFFFFFFFu, inv, r);
            uint2 u = *reinterpret_cast<const uint2*>(
                g_T + (size_t)s * TCOL + r * DIMS + lane * 4);
            float2 f0 = __half22float2(*reinterpret_cast<__half2*>(&u.x));
            float2 f1 = __half22float2(*reinterpret_cast<__half2*>(&u.y));
            acc.x += w * f0.x; acc.y += w * f0.y;
            acc.z += w * f1.x; acc.w += w * f1.y;
        }
    }
    float* o = hn + (size_t)warp * DIMS + lane * 4;
    float4 cur = *reinterpret_cast<float4*>(o);
    cur.x += acc.x; cur.y += acc.y; cur.z += acc.z; cur.w += acc.w;
    if (ah) {
        cur.x = fmaxf(cur.x, 0.f); cur.y = fmaxf(cur.y, 0.f);
        cur.z = fmaxf(cur.z, 0.f); cur.w = fmaxf(cur.w, 0.f);
        uint2 h;
        h.x = pack_h2(cur.x, cur.y);
        h.y = pack_h2(cur.z, cur.w);
        *reinterpret_cast<uint2*>(ah + (size_t)warp * DIMS + lane * 4) = h;
    } else {
        *reinterpret_cast<float4*>(o) = cur;
    }
}

// -------------------- A conversion to fragment-major fp16 --------------------
__global__ void __launch_bounds__(512)
convA_kernel(const __half* __restrict__ Ah,
             const int* __restrict__ nid,
             const float* __restrict__ emb,
             int mode) {
    extern __shared__ __half scrh[];
    const int tid = threadIdx.x;
    const int m0 = blockIdx.x * 128;

    if (mode == 0) {
        for (int i = tid; i < 128 * 32; i += 512) {
            int r = i >> 5, c4 = i & 31;
            int m = m0 + r;
            int id = nid[m < NNODES ? m : NNODES - 1];
            float4 v = reinterpret_cast<const float4*>(emb + (size_t)id * DIMS)[c4];
            uint2 h;
            h.x = pack_h2(v.x, v.y);
            h.y = pack_h2(v.z, v.w);
            *reinterpret_cast<uint2*>(&scrh[r * 128 + c4 * 4]) = h;
        }
    } else {
        for (int i = tid; i < 128 * 16; i += 512) {
            int r = i >> 4, c8 = i & 15;
            uint4 v = reinterpret_cast<const uint4*>(Ah + (size_t)(m0 + r) * DIMS)[c8];
            *reinterpret_cast<uint4*>(&scrh[r * 128 + c8 * 8]) = v;
        }
    }
    __syncthreads();

    uint4* outp = g_Afrag + (size_t)blockIdx.x * 2048;
#pragma unroll
    for (int it = 0; it < 4; it++) {
        int item = tid + it * 512;
        int bi = item >> 8;
        int kk = (item >> 5) & 7;
        int ln = item & 31;
        int q = ln >> 2, rd = ln & 3;
        int r0 = bi * 16 + q;
        int c0 = kk * 16 + rd * 2;
        uint4 w;
        w.x = *reinterpret_cast<uint32_t*>(&scrh[r0 * 128 + c0]);
        w.y = *reinterpret_cast<uint32_t*>(&scrh[(r0 + 8) * 128 + c0]);
        w.z = *reinterpret_cast<uint32_t*>(&scrh[r0 * 128 + c0 + 8]);
        w.w = *reinterpret_cast<uint32_t*>(&scrh[(r0 + 8) * 128 + c0 + 8]);
        outp[item] = w;
    }
}

// -------------------- B-stationary GEMM, group-scoped 3-stage pipeline --------
// (exact R12 configuration: best measured)
// 512 thr = 4 groups x 4 warps. Group g owns M rows [g*32, +32); bar.sync 1+g.
// 3-stage A pipeline, prefetch distance 2, B fragments hoisted to registers.
// smem: A[g][stage] = (g*3+stage)*8192 (96 KB) | B at 98304 (32 KB)
#define GEMM_SMEM 131072

__global__ void __launch_bounds__(512, 1)
gemm_kernel(const uint4* __restrict__ Afrag,
            const __half* __restrict__ B,
            __half* __restrict__ T,
            float* __restrict__ hn) {
    extern __shared__ char smc[];
    uint4* Bsm = reinterpret_cast<uint4*>(smc + 98304);
    const uint32_t sb = smem_u32(smc);

    const int tid  = threadIdx.x;
    const int nt   = blockIdx.x;
    const int mg   = blockIdx.y;
    const int mt0  = mg * MGROUP;
    const int wid  = tid >> 5;
    const int grp  = wid >> 2;          // 0..3  (M strip)
    const int wn   = wid & 3;           // 0..3  (N strip)
    const int ltid = tid & 127;
    const int lane = tid & 31;
    const int qid  = lane >> 2;
    const int rid  = lane & 3;

    const uint32_t a_base = sb + (uint32_t)grp * 3u * 8192u;
    const uint4* Atile    = Afrag + (size_t)grp * 512;

    // B tile (all threads)
    {
        const __half* Bt = B + (size_t)nt * TILE_HALVES;
#pragma unroll
        for (int it = 0; it < 4; it++) {
            int i = tid + it * 512;
            cp_async16(sb + 98304u + (uint32_t)i * 16u, Bt + i * 8);
        }
        CP_COMMIT();
    }
    // A slices for tiles 0,1 (group threads)
#pragma unroll
    for (int st = 0; st < 2; st++) {
        const uint4* At = Atile + (size_t)(mt0 + st) * 2048;
#pragma unroll
        for (int j = 0; j < 4; j++)
            cp_async16(a_base + (uint32_t)st * 8192u + (uint32_t)(ltid + j * 128) * 16u,
                       At + ltid + j * 128);
        CP_COMMIT();
    }
    CP_WAIT2();             // B done
    __syncthreads();

    // hoist B fragments to registers (reused across all 23 M tiles)
    uint4 bfr[4][4];
#pragma unroll
    for (int jn = 0; jn < 4; jn++)
#pragma unroll
        for (int kp2 = 0; kp2 < 4; kp2++)
            bfr[jn][kp2] = Bsm[(((wn * 4 + jn) * 4 + kp2) << 5) + lane];

    const int gc0 = nt * 128 + wn * 32;

    for (int mi = 0; mi < MGROUP; mi++) {
        if (mi + 1 < MGROUP) CP_WAIT1(); else CP_WAIT0();
        BAR_SYNC(1 + grp, 128);

        if (mi + 2 < MGROUP) {
            const uint4* At = Atile + (size_t)(mt0 + mi + 2) * 2048;
            uint32_t sbase = a_base + (uint32_t)((mi + 2) % 3) * 8192u;
#pragma unroll
            for (int j = 0; j < 4; j++)
                cp_async16(sbase + (uint32_t)(ltid + j * 128) * 16u,
                           At + ltid + j * 128);
            CP_COMMIT();
        }

        const uint4* Acur = reinterpret_cast<const uint4*>(
            smc + (size_t)grp * 3 * 8192 + (size_t)(mi % 3) * 8192);

        float c[2][4][4];
#pragma unroll
        for (int im = 0; im < 2; im++)
#pragma unroll
            for (int jn = 0; jn < 4; jn++)
#pragma unroll
                for (int q = 0; q < 4; q++) c[im][jn][q] = 0.f;

#pragma unroll
        for (int kk = 0; kk < 8; kk++) {
            uint4 af[2];
            af[0] = Acur[((0 * 8 + kk) << 5) + lane];
            af[1] = Acur[((1 * 8 + kk) << 5) + lane];
            int kp2 = kk >> 1;
            int sub = kk & 1;
#pragma unroll
            for (int im = 0; im < 2; im++)
#pragma unroll
                for (int jn = 0; jn < 4; jn++) {
                    uint32_t b0 = sub ? bfr[jn][kp2].z : bfr[jn][kp2].x;
                    uint32_t b1 = sub ? bfr[jn][kp2].w : bfr[jn][kp2].y;
                    mma_f16(c[im][jn], af[im], b0, b1);
                }
        }

        const int m0 = (mt0 + mi) * 128;
        if (nt == 0) {
#pragma unroll
            for (int im = 0; im < 2; im++) {
                int row = m0 + grp * 32 + im * 16 + qid;
#pragma unroll
                for (int jn = 0; jn < 4; jn++) {
                    int col = gc0 + jn * 8 + 2 * rid;
                    *reinterpret_cast<float2*>(hn + (size_t)row * DIMS + col)
                        = make_float2(c[im][jn][0], c[im][jn][1]);
                    *reinterpret_cast<float2*>(hn + (size_t)(row + 8) * DIMS + col)
                        = make_float2(c[im][jn][2], c[im][jn][3]);
                }
            }
        } else {
            int cb = gc0 - DIMS;
#pragma unroll
            for (int im = 0; im < 2; im++) {
                int row = m0 + grp * 32 + im * 16 + qid;
#pragma unroll
                for (int jn = 0; jn < 4; jn++) {
                    int col = cb + jn * 8 + 2 * rid;
                    *reinterpret_cast<__half2*>(T + (size_t)row * TCOL + col)
                        = __floats2half2_rn(c[im][jn][0], c[im][jn][1]);
                    *reinterpret_cast<__half2*>(T + (size_t)(row + 8) * TCOL + col)
                        = __floats2half2_rn(c[im][jn][2], c[im][jn][3]);
                }
            }
        }
    }
}

// -------------------- scoring (relu fused) -----------------------------------
__global__ void score_kernel(const float* __restrict__ h,
                             const int* __restrict__ heads,
                             const int* __restrict__ rels,
                             const int* __restrict__ tails,
                             const float* __restrict__ rel_emb,
                             const float* __restrict__ path_feat,
                             const int* __restrict__ task_idx,
                             const float* __restrict__ delta_w,
                             const float* __restrict__ lambda_logit,
                             const float* __restrict__ rule_init,
                             float* __restrict__ out) {
    int warp = (blockIdx.x * blockDim.x + threadIdx.x) >> 5;
    int lane = threadIdx.x & 31;
    if (warp >= NQUERY) return;
    int hh = heads[warp], rr = rels[warp], tt = tails[warp];
    float4 a = reinterpret_cast<const float4*>(h + (size_t)hh * DIMS)[lane];
    float4 r = reinterpret_cast<const float4*>(rel_emb + (size_t)rr * DIMS)[lane];
    float4 b = reinterpret_cast<const float4*>(h + (size_t)tt * DIMS)[lane];
    a.x = fmaxf(a.x, 0.f); a.y = fmaxf(a.y, 0.f); a.z = fmaxf(a.z, 0.f); a.w = fmaxf(a.w, 0.f);
    b.x = fmaxf(b.x, 0.f); b.y = fmaxf(b.y, 0.f); b.z = fmaxf(b.z, 0.f); b.w = fmaxf(b.w, 0.f);
    float s = a.x * r.x * b.x + a.y * r.y * b.y + a.z * r.z * b.z + a.w * r.w * b.w;
#pragma unroll
    for (int off = 16; off > 0; off >>= 1)
        s += __shfl_xor_sync(0xFFFFFFFFu, s, off);
    if (lane == 0) {
        int idx = task_idx[0];
        float sp = 0.f;
#pragma unroll
        for (int p = 0; p < PDIM; p++)
            sp += path_feat[warp * PDIM + p] * (rule_init[idx * PDIM + p] + delta_w[idx * PDIM + p]);
        float lam = 1.0f / (1.0f + __expf(-lambda_logit[idx]));
        out[warp] = lam * s + (1.0f - lam) * sp;
    }
}

// -------------------- launcher -----------------------------------------------
extern "C" void kernel_launch(void* const* d_in, const int* in_sizes, int n_in,
                              void* d_out, int out_size) {
    const int*   node_ids   = (const int*)d_in[0];
    const int*   edge_index = (const int*)d_in[1];
    const int*   edge_type  = (const int*)d_in[2];
    const int*   heads      = (const int*)d_in[3];
    const int*   rels       = (const int*)d_in[4];
    const int*   tails      = (const int*)d_in[5];
    const float* path_feat  = (const float*)d_in[6];
    const int*   task_idx   = (const int*)d_in[7];
    const float* entity_emb = (const float*)d_in[8];
    const float* rel_emb    = (const float*)d_in[9];
    const float* W_self     = (const float*)d_in[10];
    const float* W_rel      = (const float*)d_in[11];
    const float* delta_w    = (const float*)d_in[12];
    const float* lambda_lg  = (const float*)d_in[13];
    const float* rule_init  = (const float*)d_in[14];
    float*       out        = (float*)d_out;

    const int* src = edge_index;
    const int* dst = edge_index + NEDGE;

    float *hA, *hB;
    __half *T, *Bpack, *Ah;
    uint4* Afrag;
    cudaGetSymbolAddress((void**)&hA, g_hA);
    cudaGetSymbolAddress((void**)&hB, g_hB);
    cudaGetSymbolAddress((void**)&Ah, g_Ah);
    cudaGetSymbolAddress((void**)&T, g_T);
    cudaGetSymbolAddress((void**)&Bpack, g_Bpack);
    cudaGetSymbolAddress((void**)&Afrag, g_Afrag);

    const int TPB = 256;
    cudaFuncSetAttribute(gemm_kernel,
                         cudaFuncAttributeMaxDynamicSharedMemorySize, GEMM_SMEM);
    cudaFuncSetAttribute(convA_kernel,
                         cudaFuncAttributeMaxDynamicSharedMemorySize, 32768);

    // prep (fused pack+zero, then topology sort; scanB folded into scanC)
    prep_kernel<<<(NNODES * NRELS + TPB - 1) / TPB, TPB>>>(W_self, W_rel);
    hist_kernel<<<(NEDGE + TPB - 1) / TPB, TPB>>>(dst, edge_type);
    scanA_kernel<<<SCANB, 1024>>>();
    scanC_kernel<<<SCANB, 1024>>>();
    scatter_kernel<<<(NEDGE + TPB - 1) / TPB, TPB>>>(src, dst, edge_type);

    dim3 ggrid(NTILES, NTILES);    // 17 x 17 (R12 config)
    const int agg_blocks = (NNODES * 32 + TPB - 1) / TPB;

    // layer 1: A gathered from entity_emb; agg writes relu'd fp16 rows to Ah
    convA_kernel<<<MTILES, 512, 32768>>>(nullptr, node_ids, entity_emb, 0);
    gemm_kernel<<<ggrid, 512, GEMM_SMEM>>>(Afrag, Bpack, T, hB);
    group_agg_kernel<<<agg_blocks, TPB>>>(hB, Ah);
    // layer 2: A from fp16 Ah; agg writes fp32 hA (scoring applies relu)
    convA_kernel<<<MTILES, 512, 32768>>>(Ah, nullptr, nullptr, 1);
    gemm_kernel<<<ggrid, 512, GEMM_SMEM>>>(Afrag, Bpack + (size_t)NCOL * DIMS, T, hA);
    group_agg_kernel<<<agg_blocks, TPB>>>(hA, nullptr);

    score_kernel<<<(NQUERY * 32 + TPB - 1) / TPB, TPB>>>(
        hA, heads, rels, tails, rel_emb, path_feat, task_idx,
        delta_w, lambda_lg, rule_init, out);
}

// round 17
// speedup vs baseline: 1.6328x; 1.0047x over previous
#include <cuda_runtime.h>
#include <cuda_fp16.h>
#include <cstdint>

#define NNODES 50000
#define MPAD   50048            // 391 * 128
#define NRELS  16
#define DIMS   128
#define NLAYER 2
#define NEDGE  600000
#define NQUERY 8192
#define PDIM   5
#define NCOL   (DIMS * (NRELS + 1))   // 2176
#define TCOL   (DIMS * NRELS)         // 2048
#define NTILES 17
#define MTILES 391                    // 128-row tiles (conv layout)
#define M64TILES 782                  // 64-row tiles (GEMM)
#define MGROUP 23                     // 64-row tiles per GEMM block (34*23=782)
#define MBLKS  34
#define TILE_HALVES (128 * 128)       // fp16 per B tile (32 KB)
#define SCANB  49

// -------------------- scratch ------------------------------------------------
__device__ float  g_hA[(size_t)MPAD * DIMS];
__device__ float  g_hB[(size_t)MPAD * DIMS];
__device__ __half g_Ah[(size_t)MPAD * DIMS];              // fp16 row-major staged A
__device__ __half g_T[(size_t)MPAD * TCOL];
__device__ __half g_Bpack[NLAYER][(size_t)NCOL * DIMS];   // fragment-major fp16
__device__ uint4  g_Afrag[(size_t)MTILES * 2048];         // fragment-major fp16 A
__device__ int    g_cnt[NNODES * NRELS];
__device__ int    g_deg[NNODES];
__device__ int    g_off[NNODES + 1];
__device__ int    g_cur[NNODES];
__device__ int    g_bt[SCANB + 1];
__device__ uint32_t g_epack[NEDGE];   // src | (rel<<16)

// -------------------- helpers ------------------------------------------------
__device__ __forceinline__ uint32_t smem_u32(const void* p) {
    uint32_t a;
    asm("{ .reg .u64 t; cvta.to.shared.u64 t, %1; cvt.u32.u64 %0, t; }" : "=r"(a) : "l"(p));
    return a;
}
__device__ __forceinline__ void cp_async16(uint32_t saddr, const void* g) {
    asm volatile("cp.async.ca.shared.global [%0], [%1], 16;" :: "r"(saddr), "l"(g));
}
#define CP_COMMIT() asm volatile("cp.async.commit_group;")
#define CP_WAIT0()  asm volatile("cp.async.wait_group 0;")
#define CP_WAIT1()  asm volatile("cp.async.wait_group 1;")
#define CP_WAIT2()  asm volatile("cp.async.wait_group 2;")
#define BAR_SYNC(id, cnt) asm volatile("bar.sync %0, %1;" :: "r"(id), "r"(cnt) : "memory")

__device__ __forceinline__ uint32_t pack_h2(float a, float b) {
    __half2 h = __floats2half2_rn(a, b);
    return *reinterpret_cast<uint32_t*>(&h);
}
__device__ __forceinline__ void mma_f16(float c[4], uint4 a, uint32_t b0, uint32_t b1) {
    asm volatile(
        "mma.sync.aligned.m16n8k16.row.col.f32.f16.f16.f32 "
        "{%0,%1,%2,%3}, {%4,%5,%6,%7}, {%8,%9}, {%0,%1,%2,%3};"
        : "+f"(c[0]), "+f"(c[1]), "+f"(c[2]), "+f"(c[3])
        : "r"(a.x), "r"(a.y), "r"(a.z), "r"(a.w), "r"(b0), "r"(b1));
}

// -------------------- fused prep: weight packing + zero init ------------------
__global__ void prep_kernel(const float* __restrict__ Wself,
                            const float* __restrict__ Wrel) {
    int idx = blockIdx.x * blockDim.x + threadIdx.x;
    const int per_layer = NCOL * DIMS;
    const int total_pack = NLAYER * per_layer;
    if (idx < total_pack) {
        int l  = idx / per_layer;
        int hf = idx - l * per_layer;
        int e    = hf & 1;
        int w    = (hf >> 1) & 3;
        int lane = (hf >> 3) & 31;
        int kp2  = (hf >> 8) & 3;
        int cj   = (hf >> 10) & 15;
        int t    = hf >> 14;
        int qid = lane >> 2, rid = lane & 3;
        int kp   = kp2 * 2 + (w >> 1);
        int pair = w & 1;
        int k = kp * 16 + pair * 8 + rid * 2 + e;
        int n = t * 128 + cj * 8 + qid;
        float v;
        if (n < DIMS) {
            v = Wself[(l * DIMS + k) * DIMS + n];
        } else {
            int r = (n - DIMS) >> 7;
            int ee = (n - DIMS) & 127;
            v = Wrel[(((size_t)(l * NRELS + r) * DIMS) + k) * DIMS + ee];
        }
        g_Bpack[l][hf] = __float2half_rn(v);
    }
    if (idx < NNODES * NRELS) g_cnt[idx] = 0;
}

__global__ void hist_kernel(const int* __restrict__ dst, const int* __restrict__ et) {
    int e = blockIdx.x * blockDim.x + threadIdx.x;
    if (e >= NEDGE) return;
    atomicAdd(&g_cnt[dst[e] * NRELS + et[e]], 1);
}

// scanA: derive degree from cnt row (no per-edge deg atomics), block scan
__global__ void scanA_kernel() {
    __shared__ int s[1024];
    int t = threadIdx.x;
    int i = blockIdx.x * 1024 + t;
    int v = 0;
    if (i < NNODES) {
        const int4* c4 = reinterpret_cast<const int4*>(g_cnt + i * NRELS);
#pragma unroll
        for (int j = 0; j < 4; j++) {
            int4 u = c4[j];
            v += u.x + u.y + u.z + u.w;
        }
        g_deg[i] = v;
    }
    s[t] = v;
    __syncthreads();
#pragma unroll
    for (int off = 1; off < 1024; off <<= 1) {
        int x = (t >= off) ? s[t - off] : 0;
        __syncthreads();
        s[t] += x;
        __syncthreads();
    }
    if (i < NNODES) g_off[i + 1] = s[t];
    if (t == 1023) g_bt[blockIdx.x] = s[t];
}

__global__ void scanC_kernel() {
    __shared__ int base;
    int t = threadIdx.x;
    if (t == 0) {
        int run = 0;
        for (int b = 0; b < (int)blockIdx.x; b++) run += g_bt[b];
        base = run;
    }
    __syncthreads();
    int i = blockIdx.x * 1024 + t;
    if (i == 0) g_off[0] = 0;
    if (i < NNODES) {
        int o = g_off[i + 1] + base;
        g_off[i + 1] = o;
        g_cur[i] = o - g_deg[i];
    }
}

__global__ void scatter_kernel(const int* __restrict__ src,
                               const int* __restrict__ dst,
                               const int* __restrict__ et) {
    int e = blockIdx.x * blockDim.x + threadIdx.x;
    if (e >= NEDGE) return;
    int d = dst[e];
    int pos = atomicAdd(&g_cur[d], 1);
    g_epack[pos] = (uint32_t)src[e] | ((uint32_t)et[e] << 16);
}

// -------------------- grouped aggregation (lane-parallel, no atomics) --------
__global__ void __launch_bounds__(256)
group_agg_kernel(float* __restrict__ hn, __half* __restrict__ ah) {
    int warp = (blockIdx.x * blockDim.x + threadIdx.x) >> 5;
    int lane = threadIdx.x & 31;
    if (warp >= NNODES) return;
    int beg = g_off[warp];
    int end = g_off[warp + 1];
    if (!ah && beg == end) return;

    float inv = 0.f;
    if (lane < NRELS) {
        int c = g_cnt[warp * NRELS + lane];
        inv = (c > 0) ? (1.0f / (float)c) : 0.f;
    }

    float4 acc = make_float4(0.f, 0.f, 0.f, 0.f);
    for (int base = beg; base < end; base += 32) {
        int m = min(32, end - base);
        uint32_t myp = (lane < m) ? g_epack[base + lane] : 0u;
        for (int i = 0; i < m; i++) {
            uint32_t p = __shfl_sync(0xFFFFFFFFu, myp, i);
            int s = p & 0xFFFF;
            int r = p >> 16;
            float w = __shfl_sync(0xFFFFFFFFu, inv, r);
            uint2 u = *reinterpret_cast<const uint2*>(
                g_T + (size_t)s * TCOL + r * DIMS + lane * 4);
            float2 f0 = __half22float2(*reinterpret_cast<__half2*>(&u.x));
            float2 f1 = __half22float2(*reinterpret_cast<__half2*>(&u.y));
            acc.x += w * f0.x; acc.y += w * f0.y;
            acc.z += w * f1.x; acc.w += w * f1.y;
        }
    }
    float* o = hn + (size_t)warp * DIMS + lane * 4;
    float4 cur = *reinterpret_cast<float4*>(o);
    cur.x += acc.x; cur.y += acc.y; cur.z += acc.z; cur.w += acc.w;
    if (ah) {
        cur.x = fmaxf(cur.x, 0.f); cur.y = fmaxf(cur.y, 0.f);
        cur.z = fmaxf(cur.z, 0.f); cur.w = fmaxf(cur.w, 0.f);
        uint2 h;
        h.x = pack_h2(cur.x, cur.y);
        h.y = pack_h2(cur.z, cur.w);
        *reinterpret_cast<uint2*>(ah + (size_t)warp * DIMS + lane * 4) = h;
    } else {
        *reinterpret_cast<float4*>(o) = cur;
    }
}

// -------------------- A conversion to fragment-major fp16 --------------------
__global__ void __launch_bounds__(512)
convA_kernel(const __half* __restrict__ Ah,
             const int* __restrict__ nid,
             const float* __restrict__ emb,
             int mode) {
    extern __shared__ __half scrh[];
    const int tid = threadIdx.x;
    const int m0 = blockIdx.x * 128;

    if (mode == 0) {
        for (int i = tid; i < 128 * 32; i += 512) {
            int r = i >> 5, c4 = i & 31;
            int m = m0 + r;
            int id = nid[m < NNODES ? m : NNODES - 1];
            float4 v = reinterpret_cast<const float4*>(emb + (size_t)id * DIMS)[c4];
            uint2 h;
            h.x = pack_h2(v.x, v.y);
            h.y = pack_h2(v.z, v.w);
            *reinterpret_cast<uint2*>(&scrh[r * 128 + c4 * 4]) = h;
        }
    } else {
        for (int i = tid; i < 128 * 16; i += 512) {
            int r = i >> 4, c8 = i & 15;
            uint4 v = reinterpret_cast<const uint4*>(Ah + (size_t)(m0 + r) * DIMS)[c8];
            *reinterpret_cast<uint4*>(&scrh[r * 128 + c8 * 8]) = v;
        }
    }
    __syncthreads();

    uint4* outp = g_Afrag + (size_t)blockIdx.x * 2048;
#pragma unroll
    for (int it = 0; it < 4; it++) {
        int item = tid + it * 512;
        int bi = item >> 8;
        int kk = (item >> 5) & 7;
        int ln = item & 31;
        int q = ln >> 2, rd = ln & 3;
        int r0 = bi * 16 + q;
        int c0 = kk * 16 + rd * 2;
        uint4 w;
        w.x = *reinterpret_cast<uint32_t*>(&scrh[r0 * 128 + c0]);
        w.y = *reinterpret_cast<uint32_t*>(&scrh[(r0 + 8) * 128 + c0]);
        w.z = *reinterpret_cast<uint32_t*>(&scrh[r0 * 128 + c0 + 8]);
        w.w = *reinterpret_cast<uint32_t*>(&scrh[(r0 + 8) * 128 + c0 + 8]);
        outp[item] = w;
    }
}

// -------------------- B-stationary GEMM, 256 thr, 2 CTAs/SM -------------------
// R12 pipeline (3-stage, distance-2, group-scoped named barriers, hoisted B)
// with half-size CTA: 2 M-groups (64 rows/tile) x 4 N-warps. grid 17 x 34.
// smem: A[g][stage] = (g*3+stage)*8192 (48 KB) | B at 49152 (32 KB) = 80 KB
#define GEMM_SMEM 81920

__global__ void __launch_bounds__(256, 2)
gemm_kernel(const uint4* __restrict__ Afrag,
            const __half* __restrict__ B,
            __half* __restrict__ T,
            float* __restrict__ hn) {
    extern __shared__ char smc[];
    uint4* Bsm = reinterpret_cast<uint4*>(smc + 49152);
    const uint32_t sb = smem_u32(smc);

    const int tid  = threadIdx.x;
    const int nt   = blockIdx.x;        // 0..16
    const int mg   = blockIdx.y;        // 0..33
    const int mt0  = mg * MGROUP;       // in 64-row tiles
    const int wid  = tid >> 5;          // 0..7
    const int grp  = wid >> 2;          // 0..1 (M strip)
    const int wn   = wid & 3;           // 0..3 (N strip)
    const int ltid = tid & 127;
    const int lane = tid & 31;
    const int qid  = lane >> 2;
    const int rid  = lane & 3;

    const uint32_t a_base = sb + (uint32_t)grp * 3u * 8192u;

    // slice pointer for 64-row tile m64: Afrag[(m64>>1)*2048 + ((m64&1)*2+grp)*512]
    // B tile (all threads)
    {
        const __half* Bt = B + (size_t)nt * TILE_HALVES;
#pragma unroll
        for (int it = 0; it < 8; it++) {
            int i = tid + it * 256;
            cp_async16(sb + 49152u + (uint32_t)i * 16u, Bt + i * 8);
        }
        CP_COMMIT();
    }
    // A slices for tiles 0,1 (group threads)
#pragma unroll
    for (int st = 0; st < 2; st++) {
        int m64 = mt0 + st;
        const uint4* At = Afrag + (size_t)(m64 >> 1) * 2048
                                + (size_t)((m64 & 1) * 2 + grp) * 512;
#pragma unroll
        for (int j = 0; j < 4; j++)
            cp_async16(a_base + (uint32_t)st * 8192u + (uint32_t)(ltid + j * 128) * 16u,
                       At + ltid + j * 128);
        CP_COMMIT();
    }
    CP_WAIT2();             // B done
    __syncthreads();

    // hoist B fragments to registers
    uint4 bfr[4][4];
#pragma unroll
    for (int jn = 0; jn < 4; jn++)
#pragma unroll
        for (int kp2 = 0; kp2 < 4; kp2++)
            bfr[jn][kp2] = Bsm[(((wn * 4 + jn) * 4 + kp2) << 5) + lane];

    const int gc0 = nt * 128 + wn * 32;

    for (int mi = 0; mi < MGROUP; mi++) {
        if (mi + 1 < MGROUP) CP_WAIT1(); else CP_WAIT0();
        BAR_SYNC(1 + grp, 128);

        if (mi + 2 < MGROUP) {
            int m64 = mt0 + mi + 2;
            const uint4* At = Afrag + (size_t)(m64 >> 1) * 2048
                                    + (size_t)((m64 & 1) * 2 + grp) * 512;
            uint32_t sbase = a_base + (uint32_t)((mi + 2) % 3) * 8192u;
#pragma unroll
            for (int j = 0; j < 4; j++)
                cp_async16(sbase + (uint32_t)(ltid + j * 128) * 16u,
                           At + ltid + j * 128);
            CP_COMMIT();
        }

        const uint4* Acur = reinterpret_cast<const uint4*>(
            smc + (size_t)grp * 3 * 8192 + (size_t)(mi % 3) * 8192);

        float c[2][4][4];
#pragma unroll
        for (int im = 0; im < 2; im++)
#pragma unroll
            for (int jn = 0; jn < 4; jn++)
#pragma unroll
                for (int q = 0; q < 4; q++) c[im][jn][q] = 0.f;

#pragma unroll
        for (int kk = 0; kk < 8; kk++) {
            uint4 af[2];
            af[0] = Acur[((0 * 8 + kk) << 5) + lane];
            af[1] = Acur[((1 * 8 + kk) << 5) + lane];
            int kp2 = kk >> 1;
            int sub = kk & 1;
#pragma unroll
            for (int im = 0; im < 2; im++)
#pragma unroll
                for (int jn = 0; jn < 4; jn++) {
                    uint32_t b0 = sub ? bfr[jn][kp2].z : bfr[jn][kp2].x;
                    uint32_t b1 = sub ? bfr[jn][kp2].w : bfr[jn][kp2].y;
                    mma_f16(c[im][jn], af[im], b0, b1);
                }
        }

        const int m0 = (mt0 + mi) * 64 + grp * 32;   // slice covers 32 rows
        if (nt == 0) {
#pragma unroll
            for (int im = 0; im < 2; im++) {
                int row = m0 + im * 16 + qid;
#pragma unroll
                for (int jn = 0; jn < 4; jn++) {
                    int col = gc0 + jn * 8 + 2 * rid;
                    *reinterpret_cast<float2*>(hn + (size_t)row * DIMS + col)
                        = make_float2(c[im][jn][0], c[im][jn][1]);
                    *reinterpret_cast<float2*>(hn + (size_t)(row + 8) * DIMS + col)
                        = make_float2(c[im][jn][2], c[im][jn][3]);
                }
            }
        } else {
            int cb = gc0 - DIMS;
#pragma unroll
            for (int im = 0; im < 2; im++) {
                int row = m0 + im * 16 + qid;
#pragma unroll
                for (int jn = 0; jn < 4; jn++) {
                    int col = cb + jn * 8 + 2 * rid;
                    *reinterpret_cast<__half2*>(T + (size_t)row * TCOL + col)
                        = __floats2half2_rn(c[im][jn][0], c[im][jn][1]);
                    *reinterpret_cast<__half2*>(T + (size_t)(row + 8) * TCOL + col)
                        = __floats2half2_rn(c[im][jn][2], c[im][jn][3]);
                }
            }
        }
    }
}

// -------------------- scoring (relu fused) -----------------------------------
__global__ void score_kernel(const float* __restrict__ h,
                             const int* __restrict__ heads,
                             const int* __restrict__ rels,
                             const int* __restrict__ tails,
                             const float* __restrict__ rel_emb,
                             const float* __restrict__ path_feat,
                             const int* __restrict__ task_idx,
                             const float* __restrict__ delta_w,
                             const float* __restrict__ lambda_logit,
                             const float* __restrict__ rule_init,
                             float* __restrict__ out) {
    int warp = (blockIdx.x * blockDim.x + threadIdx.x) >> 5;
    int lane = threadIdx.x & 31;
    if (warp >= NQUERY) return;
    int hh = heads[warp], rr = rels[warp], tt = tails[warp];
    float4 a = reinterpret_cast<const float4*>(h + (size_t)hh * DIMS)[lane];
    float4 r = reinterpret_cast<const float4*>(rel_emb + (size_t)rr * DIMS)[lane];
    float4 b = reinterpret_cast<const float4*>(h + (size_t)tt * DIMS)[lane];
    a.x = fmaxf(a.x, 0.f); a.y = fmaxf(a.y, 0.f); a.z = fmaxf(a.z, 0.f); a.w = fmaxf(a.w, 0.f);
    b.x = fmaxf(b.x, 0.f); b.y = fmaxf(b.y, 0.f); b.z = fmaxf(b.z, 0.f); b.w = fmaxf(b.w, 0.f);
    float s = a.x * r.x * b.x + a.y * r.y * b.y + a.z * r.z * b.z + a.w * r.w * b.w;
#pragma unroll
    for (int off = 16; off > 0; off >>= 1)
        s += __shfl_xor_sync(0xFFFFFFFFu, s, off);
    if (lane == 0) {
        int idx = task_idx[0];
        float sp = 0.f;
#pragma unroll
        for (int p = 0; p < PDIM; p++)
            sp += path_feat[warp * PDIM + p] * (rule_init[idx * PDIM + p] + delta_w[idx * PDIM + p]);
        float lam = 1.0f / (1.0f + __expf(-lambda_logit[idx]));
        out[warp] = lam * s + (1.0f - lam) * sp;
    }
}

// -------------------- launcher -----------------------------------------------
extern "C" void kernel_launch(void* const* d_in, const int* in_sizes, int n_in,
                              void* d_out, int out_size) {
    const int*   node_ids   = (const int*)d_in[0];
    const int*   edge_index = (const int*)d_in[1];
    const int*   edge_type  = (const int*)d_in[2];
    const int*   heads      = (const int*)d_in[3];
    const int*   rels       = (const int*)d_in[4];
    const int*   tails      = (const int*)d_in[5];
    const float* path_feat  = (const float*)d_in[6];
    const int*   task_idx   = (const int*)d_in[7];
    const float* entity_emb = (const float*)d_in[8];
    const float* rel_emb    = (const float*)d_in[9];
    const float* W_self     = (const float*)d_in[10];
    const float* W_rel      = (const float*)d_in[11];
    const float* delta_w    = (const float*)d_in[12];
    const float* lambda_lg  = (const float*)d_in[13];
    const float* rule_init  = (const float*)d_in[14];
    float*       out        = (float*)d_out;

    const int* src = edge_index;
    const int* dst = edge_index + NEDGE;

    float *hA, *hB;
    __half *T, *Bpack, *Ah;
    uint4* Afrag;
    cudaGetSymbolAddress((void**)&hA, g_hA);
    cudaGetSymbolAddress((void**)&hB, g_hB);
    cudaGetSymbolAddress((void**)&Ah, g_Ah);
    cudaGetSymbolAddress((void**)&T, g_T);
    cudaGetSymbolAddress((void**)&Bpack, g_Bpack);
    cudaGetSymbolAddress((void**)&Afrag, g_Afrag);

    const int TPB = 256;
    cudaFuncSetAttribute(gemm_kernel,
                         cudaFuncAttributeMaxDynamicSharedMemorySize, GEMM_SMEM);
    cudaFuncSetAttribute(convA_kernel,
                         cudaFuncAttributeMaxDynamicSharedMemorySize, 32768);

    prep_kernel<<<(NNODES * NRELS + TPB - 1) / TPB, TPB>>>(W_self, W_rel);
    hist_kernel<<<(NEDGE + TPB - 1) / TPB, TPB>>>(dst, edge_type);
    scanA_kernel<<<SCANB, 1024>>>();
    scanC_kernel<<<SCANB, 1024>>>();
    scatter_kernel<<<(NEDGE + TPB - 1) / TPB, TPB>>>(src, dst, edge_type);

    dim3 ggrid(NTILES, MBLKS);     // 17 x 34 = 578 blocks, 2 CTAs/SM
    const int agg_blocks = (NNODES * 32 + TPB - 1) / TPB;

    // layer 1: A gathered from entity_emb; agg writes relu'd fp16 rows to Ah
    convA_kernel<<<MTILES, 512, 32768>>>(nullptr, node_ids, entity_emb, 0);
    gemm_kernel<<<ggrid, 256, GEMM_SMEM>>>(Afrag, Bpack, T, hB);
    group_agg_kernel<<<agg_blocks, TPB>>>(hB, Ah);
    // layer 2: A from fp16 Ah; agg writes fp32 hA (scoring applies relu)
    convA_kernel<<<MTILES, 512, 32768>>>(Ah, nullptr, nullptr, 1);
    gemm_kernel<<<ggrid, 256, GEMM_SMEM>>>(Afrag, Bpack + (size_t)NCOL * DIMS, T, hA);
    group_agg_kernel<<<agg_blocks, TPB>>>(hA, nullptr);

    score_kernel<<<(NQUERY * 32 + TPB - 1) / TPB, TPB>>>(
        hA, heads, rels, tails, rel_emb, path_feat, task_idx,
        delta_w, lambda_lg, rule_init, out);
}